// round 10
// baseline (speedup 1.0000x reference)
#include <cuda_runtime.h>
#include <math.h>

// Shapes (fixed by dataset):
//   features: [B=2, C=512, H=50, W=64] float32
//   roiss   : [B=2, N=128, 4]          float32
//   out     : [B, N, C]                float32
#define BB 2
#define CC 512
#define HH 50
#define WW 64
#define NN 128
#define HWSZ (HH * WW)   // 3200

// ---------------------------------------------------------------------------
// Fused ROI max-pool, original [B, C, H, W] layout.
//   grid  = (B*N, 4)  — blockIdx.x = roi, blockIdx.y = 128-channel tile
//   block = 256       — 8 warps; warp: 16 channels x 2 chunk-lanes
// Window width <= 7 -> 8-float span aligned to 2 (x1 & ~1) covers it.
// Each thread owns TWO float2 chunks of that span (half=0: cols {0,1,4,5};
// half=1: cols {2,3,6,7}) x up to 8 predicated rows -> up to 16 independent
// LDG.64 in flight. Box computed once per block; column validity applied
// once at the end; one shfl_xor(1) combines the two chunk lanes.
// ---------------------------------------------------------------------------
struct Box { int x1, xe, y1, ye, xa; };

__global__ __launch_bounds__(256) void roipool_fused_kernel(
    const float* __restrict__ feat,
    const float* __restrict__ rois,
    float* __restrict__ out)
{
    const int bn   = blockIdx.x;            // 0 .. B*N-1
    const int b    = bn / NN;
    const int w    = threadIdx.x >> 5;      // warp 0..7
    const int lane = threadIdx.x & 31;
    const int csub = lane >> 1;             // 0..15 channel within warp
    const int half = lane & 1;              // 0..1  chunk-lane
    const int c    = blockIdx.y * 128 + w * 16 + csub;

    __shared__ Box sbox;

    if (threadIdx.x == 0) {
        // --- box computation (byte-identical to jax reference path) ---
        const float4 r = reinterpret_cast<const float4*>(rois)[bn];
        const float nx1 = __fmul_rn(__fdiv_rn(r.x, 1024.0f), (float)WW);
        const float ny1 = __fmul_rn(__fdiv_rn(r.y,  800.0f), (float)HH);
        const float nx2 = __fmul_rn(__fdiv_rn(r.z, 1024.0f), (float)WW);
        const float ny2 = __fmul_rn(__fdiv_rn(r.w,  800.0f), (float)HH);

        int x1 = max((int)floorf(nx1), 0);
        int y1 = max((int)floorf(ny1), 0);
        int x2 = max((int)ceilf(nx2), 0);
        int y2 = max((int)ceilf(ny2), 0);

        if (x1 == 0 && x2 == 0) x2 = 1;
        if (y1 == 0 && y2 == 0) y2 = 1;
        if (x1 >= WW) x1 = WW - 1;
        if (y1 >= HH) y1 = HH - 1;

        sbox.x1 = x1;
        sbox.xe = min(x2, WW);
        sbox.y1 = y1;
        sbox.ye = min(y2, HH);
        sbox.xa = x1 & ~1;                  // 8B-aligned window start
    }
    __syncthreads();

    const int x1 = sbox.x1, xe = sbox.xe, y1 = sbox.y1, ye = sbox.ye;
    const int hgt = ye - y1;                // window rows (<= 7 here)
    const int xb0 = sbox.xa + half * 2;     // first chunk of this lane
    const int xb1 = xb0 + 4;                // second chunk of this lane
    const bool ok0 = (xb0 < xe);
    const bool ok1 = (xb1 < xe);

    const float* base = feat + ((size_t)(b * CC + c)) * HWSZ + y1 * WW;

    float a0 = -INFINITY, a1 = -INFINITY;   // chunk 0 components
    float d0 = -INFINITY, d1 = -INFINITY;   // chunk 1 components

    // Up to 16 independent predicated LDG.64 (2 chunks x 8 rows).
    #pragma unroll
    for (int j = 0; j < 8; ++j) {
        if (j < hgt) {
            if (ok0) {
                const float2 v =
                    *reinterpret_cast<const float2*>(base + j * WW + xb0);
                a0 = fmaxf(a0, v.x);
                a1 = fmaxf(a1, v.y);
            }
            if (ok1) {
                const float2 v =
                    *reinterpret_cast<const float2*>(base + j * WW + xb1);
                d0 = fmaxf(d0, v.x);
                d1 = fmaxf(d1, v.y);
            }
        }
    }
    // Safety tail for taller windows (never taken with these shapes)
    for (int j = 8; j < hgt; ++j) {
        if (ok0) {
            const float2 v =
                *reinterpret_cast<const float2*>(base + j * WW + xb0);
            a0 = fmaxf(a0, v.x); a1 = fmaxf(a1, v.y);
        }
        if (ok1) {
            const float2 v =
                *reinterpret_cast<const float2*>(base + j * WW + xb1);
            d0 = fmaxf(d0, v.x); d1 = fmaxf(d1, v.y);
        }
    }
    // Safety tail for windows wider than the 8-float span (never taken)
    for (int xx = sbox.xa + 8 + half; xx < xe; xx += 2)
        for (int j = 0; j < hgt; ++j)
            a0 = fmaxf(a0, __ldg(base + j * WW + xx));

    // Apply column validity once: components sit at xb0, xb0+1, xb1, xb1+1.
    const float v0 = (xb0 + 0 >= x1 && xb0 + 0 < xe) ? a0 : -INFINITY;
    const float v1 = (xb0 + 1 >= x1 && xb0 + 1 < xe) ? a1 : -INFINITY;
    const float v2 = (xb1 + 0 >= x1 && xb1 + 0 < xe) ? d0 : -INFINITY;
    const float v3 = (xb1 + 1 >= x1 && xb1 + 1 < xe) ? d1 : -INFINITY;
    float v = fmaxf(fmaxf(v0, v1), fmaxf(v2, v3));

    // Combine the two chunk lanes.
    v = fmaxf(v, __shfl_xor_sync(0xFFFFFFFFu, v, 1));

    if (half == 0)
        out[(size_t)bn * CC + c] = v;       // 16 lanes/warp -> 64B contiguous
}

extern "C" void kernel_launch(void* const* d_in, const int* in_sizes, int n_in,
                              void* d_out, int out_size)
{
    const float* feat = (const float*)d_in[0];   // [B, C, H, W]
    const float* rois = (const float*)d_in[1];   // [B, N, 4]
    float* out        = (float*)d_out;           // [B, N, C]
    (void)in_sizes; (void)n_in; (void)out_size;

    dim3 grid(BB * NN, CC / 128);                // 256 x 4 = 1024 blocks
    roipool_fused_kernel<<<grid, 256>>>(feat, rois, out);
}

// round 11
// speedup vs baseline: 1.2362x; 1.2362x over previous
#include <cuda_runtime.h>
#include <math.h>

// Shapes (fixed by dataset):
//   features: [B=2, C=512, H=50, W=64] float32
//   roiss   : [B=2, N=128, 4]          float32
//   out     : [B, N, C]                float32
#define BB 2
#define CC 512
#define HH 50
#define WW 64
#define NN 128
#define HWSZ (HH * WW)   // 3200
#define WPAD 68          // padded smem row (floats): even (float2 align) and
                         // 4-bank shift per row -> conflict-free 8-row access

// ---------------------------------------------------------------------------
// Plane-staged ROI max-pool.
//   grid  = B*C = 1024 blocks; block = 256 (8 warps).
//   Phase 1: stage the (b,c) H x W plane into smem, coalesced float2.
//   Phase 2: threads 0..127 compute the 128 ROI boxes into smem.
//   Phase 3: each warp answers 8 ROIs at a time (lane = roi_sub*4 + chunk),
//            2 passes -> 16 ROIs/warp, 128/block. Window width <= 7 fits the
//            8-float span aligned to 2 (4 float2 chunks); rows <= 7 via 8
//            predicated smem loads. 2x shfl_xor reduce; chunk==0 stores.
// Global traffic: exactly 13.1 MB, fully sequential.
// ---------------------------------------------------------------------------
__global__ __launch_bounds__(256, 8) void roipool_plane_kernel(
    const float* __restrict__ feat,
    const float* __restrict__ rois,
    float* __restrict__ out)
{
    __shared__ float plane[HH][WPAD];
    __shared__ int4  sbox[NN];          // x1, xe, y1, ye

    const int b   = blockIdx.x >> 9;    // 0..1
    const int c   = blockIdx.x & 511;   // 0..511
    const int tid = threadIdx.x;

    // ---- Phase 1: stage plane (3200 floats) into smem, coalesced ----
    const float2* src = reinterpret_cast<const float2*>(
        feat + (size_t)(b * CC + c) * HWSZ);
    #pragma unroll
    for (int i = tid; i < HWSZ / 2; i += 256) {
        const float2 v = src[i];
        const int row = i >> 5;                  // 32 float2 per row
        const int col = (i & 31) * 2;
        *reinterpret_cast<float2*>(&plane[row][col]) = v;
    }

    // ---- Phase 2: boxes (byte-identical to jax reference path) ----
    if (tid < NN) {
        const float4 r =
            reinterpret_cast<const float4*>(rois)[b * NN + tid];
        const float nx1 = __fmul_rn(__fdiv_rn(r.x, 1024.0f), (float)WW);
        const float ny1 = __fmul_rn(__fdiv_rn(r.y,  800.0f), (float)HH);
        const float nx2 = __fmul_rn(__fdiv_rn(r.z, 1024.0f), (float)WW);
        const float ny2 = __fmul_rn(__fdiv_rn(r.w,  800.0f), (float)HH);

        int x1 = max((int)floorf(nx1), 0);
        int y1 = max((int)floorf(ny1), 0);
        int x2 = max((int)ceilf(nx2), 0);
        int y2 = max((int)ceilf(ny2), 0);

        if (x1 == 0 && x2 == 0) x2 = 1;
        if (y1 == 0 && y2 == 0) y2 = 1;
        if (x1 >= WW) x1 = WW - 1;
        if (y1 >= HH) y1 = HH - 1;

        sbox[tid] = make_int4(x1, min(x2, WW), y1, min(y2, HH));
    }
    __syncthreads();

    // ---- Phase 3: answer ROIs from smem ----
    const int w     = tid >> 5;         // warp 0..7
    const int lane  = tid & 31;
    const int rsub  = lane >> 2;        // 0..7 roi slot within warp
    const int chunk = lane & 3;         // 0..3 float2 chunk

    #pragma unroll
    for (int pass = 0; pass < 2; ++pass) {
        const int n = w * 16 + pass * 8 + rsub;     // this lane-group's ROI
        const int4 bx = sbox[n];
        const int x1 = bx.x, xe = bx.y, y1 = bx.z, ye = bx.w;
        const int hgt = ye - y1;                    // <= 7 here
        const int xa  = x1 & ~1;                    // 8B-aligned span start
        const int xb  = xa + chunk * 2;
        const bool ok = (xb < xe);

        float m0 = -INFINITY, m1 = -INFINITY;

        // rows: 8 predicated smem float2 loads (height <= 7 here)
        #pragma unroll
        for (int j = 0; j < 8; ++j) {
            if (ok && j < hgt) {
                const float2 v =
                    *reinterpret_cast<const float2*>(&plane[y1 + j][xb]);
                m0 = fmaxf(m0, v.x);
                m1 = fmaxf(m1, v.y);
            }
        }
        // safety tails (never taken with these shapes)
        for (int j = 8; j < hgt; ++j) {
            if (ok) {
                const float2 v =
                    *reinterpret_cast<const float2*>(&plane[y1 + j][xb]);
                m0 = fmaxf(m0, v.x);
                m1 = fmaxf(m1, v.y);
            }
        }
        for (int xx = xa + 8 + chunk; xx < xe; xx += 4)
            for (int j = 0; j < hgt; ++j)
                m0 = fmaxf(m0, plane[y1 + j][xx]);

        // column validity once: components at xb, xb+1
        const float v0 = (xb + 0 >= x1 && xb + 0 < xe) ? m0 : -INFINITY;
        const float v1 = (xb + 1 >= x1 && xb + 1 < xe) ? m1 : -INFINITY;
        float v = fmaxf(v0, v1);

        // reduce across the 4 chunk lanes (stays within the lane-group)
        v = fmaxf(v, __shfl_xor_sync(0xFFFFFFFFu, v, 1));
        v = fmaxf(v, __shfl_xor_sync(0xFFFFFFFFu, v, 2));

        if (chunk == 0)
            out[(size_t)(b * NN + n) * CC + c] = v;
    }
}

extern "C" void kernel_launch(void* const* d_in, const int* in_sizes, int n_in,
                              void* d_out, int out_size)
{
    const float* feat = (const float*)d_in[0];   // [B, C, H, W]
    const float* rois = (const float*)d_in[1];   // [B, N, 4]
    float* out        = (float*)d_out;           // [B, N, C]
    (void)in_sizes; (void)n_in; (void)out_size;

    roipool_plane_kernel<<<BB * CC, 256>>>(feat, rois, out);
}